// round 4
// baseline (speedup 1.0000x reference)
#include <cuda_runtime.h>
#include <cstdint>

// Problem dims
#define B_DIM 16384
#define K_DIM 256
#define N_DIM 4096

// Tile config: CTA 128x128, warp grid 4(M) x 2(N), warp tile 32x64
#define BM 128
#define BN 128
#define BK 32                       // fp32 per K-chunk (one 128B permuted row-chunk)
#define NCHUNK (K_DIM / BK)         // 8
#define NSTAGE 3
#define A_STAGE_BYTES (BM * 128)    // 16 KB
#define B_STAGE_BYTES (BN * 128)    // 16 KB
#define STAGE_BYTES (A_STAGE_BYTES + B_STAGE_BYTES)  // 32 KB
#define SMEM_TOTAL (NSTAGE * STAGE_BYTES)            // 96 KB

// Scratch (no allocation allowed): tf32-rounded, K-permuted copies of x and W.
// Permuted K layout within each 32-wide chunk: kp = (k%4)*8 + (k%32)/4.
// This makes every mma fragment gather a single ld.shared.v4.b32.
__device__ float g_xt[B_DIM * K_DIM];   // [B][Kperm]
__device__ float g_w2[N_DIM * K_DIM];   // [N][Kperm], source W[s][o][cg], k = s*8+cg

// ---------------- helpers ----------------
static __device__ __forceinline__ uint32_t smem_u32(const void* p) {
    uint32_t a;
    asm("{ .reg .u64 t; cvta.to.shared.u64 t, %1; cvt.u32.u64 %0, t; }" : "=r"(a) : "l"(p));
    return a;
}
static __device__ __forceinline__ float tf32_rna(float v) {
    uint32_t u;
    asm("cvt.rna.tf32.f32 %0, %1;" : "=r"(u) : "f"(v));
    return __uint_as_float(u);
}
static __device__ __forceinline__ void lds128(uint32_t* r, uint32_t addr) {
    asm volatile("ld.shared.v4.b32 {%0,%1,%2,%3}, [%4];"
                 : "=r"(r[0]), "=r"(r[1]), "=r"(r[2]), "=r"(r[3]) : "r"(addr));
}
static __device__ __forceinline__ void mma8(float* d,
                                            uint32_t a0, uint32_t a1, uint32_t a2, uint32_t a3,
                                            uint32_t b0, uint32_t b1) {
    asm volatile(
        "mma.sync.aligned.m16n8k8.row.col.f32.tf32.tf32.f32 "
        "{%0,%1,%2,%3}, {%4,%5,%6,%7}, {%8,%9}, {%0,%1,%2,%3};"
        : "+f"(d[0]), "+f"(d[1]), "+f"(d[2]), "+f"(d[3])
        : "r"(a0), "r"(a1), "r"(a2), "r"(a3), "r"(b0), "r"(b1));
}
static __device__ __forceinline__ void cp16(uint32_t dst, const void* src) {
    asm volatile("cp.async.cg.shared.global [%0], [%1], 16;" :: "r"(dst), "l"(src) : "memory");
}

// Load one K-chunk (A: 128x32, B: 128x32 permuted floats) into a stage.
// 16B-chunk XOR swizzle by (row & 7) -> conflict-free fragment lds.128 later.
static __device__ __forceinline__ void load_chunk(int tid, int m0, int n0, int kc, uint32_t stage) {
#pragma unroll
    for (int i = 0; i < 4; i++) {          // A: 1024 16B chunks
        int id = tid + i * 256;
        int m = id >> 3, w = id & 7;
        const float* src = g_xt + (size_t)(m0 + m) * K_DIM + kc * BK + w * 4;
        uint32_t dst = stage + (uint32_t)(m * 128 + ((w ^ (m & 7)) << 4));
        cp16(dst, src);
    }
#pragma unroll
    for (int i = 0; i < 4; i++) {          // B: 1024 16B chunks
        int id = tid + i * 256;
        int n = id >> 3, w = id & 7;
        const float* src = g_w2 + (size_t)(n0 + n) * K_DIM + kc * BK + w * 4;
        uint32_t dst = stage + A_STAGE_BYTES + (uint32_t)(n * 128 + ((w ^ (n & 7)) << 4));
        cp16(dst, src);
    }
    asm volatile("cp.async.commit_group;" ::: "memory");
}

// ---------------- repack kernels (tf32 RNA + K-permute) ----------------
__global__ void __launch_bounds__(256) repack_x_k(const float* __restrict__ x) {
    int i = blockIdx.x * blockDim.x + threadIdx.x;    // over B*K
    int b = i >> 8, kp = i & 255;
    int kin = kp & 31, cc = kin >> 3, t = kin & 7;
    int k = (kp & ~31) + t * 4 + cc;
    g_xt[i] = tf32_rna(x[b * K_DIM + k]);
}
__global__ void __launch_bounds__(256) repack_w_k(const float* __restrict__ W) {
    int i = blockIdx.x * blockDim.x + threadIdx.x;    // over N*K
    int n = i >> 8, kp = i & 255;
    int kin = kp & 31, cc = kin >> 3, t = kin & 7;
    int k = (kp & ~31) + t * 4 + cc;
    int s = k >> 3, cg = k & 7;
    g_w2[i] = tf32_rna(W[s * (N_DIM * 8) + n * 8 + cg]);
}

// ---------------- main GEMM kernel ----------------
__global__ void __launch_bounds__(256, 2) slb_gemm(float* __restrict__ out) {
    extern __shared__ char smem[];
    const uint32_t sb = smem_u32(smem);
    const int tid = threadIdx.x;
    const int lane = tid & 31;
    const int wid = tid >> 5;
    const int g = lane >> 2;          // fragment group row
    const int c = lane & 3;           // fragment group col
    const int wm = wid & 3;           // warp M index (4)
    const int wn = wid >> 2;          // warp N index (2)

    const int m0 = (int)(blockIdx.x >> 5) * BM;
    const int n0 = (int)(blockIdx.x & 31) * BN;

    float acc[2][8][4];
#pragma unroll
    for (int mt = 0; mt < 2; mt++)
#pragma unroll
        for (int nt = 0; nt < 8; nt++)
#pragma unroll
            for (int e = 0; e < 4; e++) acc[mt][nt][e] = 0.0f;

    // Prologue: chunks 0,1
    load_chunk(tid, m0, n0, 0, sb);
    load_chunk(tid, m0, n0, 1, sb + STAGE_BYTES);

    // Per-thread row byte offsets (relative to stage base)
    uint32_t arel[4], brel[8];
#pragma unroll
    for (int rg = 0; rg < 4; rg++) arel[rg] = (uint32_t)((wm * 32 + g + rg * 8) * 128);
#pragma unroll
    for (int nt = 0; nt < 8; nt++)
        brel[nt] = (uint32_t)(A_STAGE_BYTES + (wn * 64 + nt * 8 + g) * 128);

#pragma unroll
    for (int kc = 0; kc < NCHUNK; kc++) {
        if (kc < NCHUNK - 1) asm volatile("cp.async.wait_group 1;" ::: "memory");
        else                 asm volatile("cp.async.wait_group 0;" ::: "memory");
        __syncthreads();
        if (kc + 2 < NCHUNK)
            load_chunk(tid, m0, n0, kc + 2, sb + (uint32_t)(((kc + 2) % NSTAGE) * STAGE_BYTES));

        const uint32_t st = sb + (uint32_t)((kc % NSTAGE) * STAGE_BYTES);
#pragma unroll
        for (int jh = 0; jh < 2; jh++) {
            const uint32_t chk = (uint32_t)(((2 * c + jh) ^ g) << 4);
            uint32_t a[4][4];
#pragma unroll
            for (int rg = 0; rg < 4; rg++) lds128(a[rg], st + arel[rg] + chk);
#pragma unroll
            for (int nh = 0; nh < 2; nh++) {
                uint32_t b[4][4];
#pragma unroll
                for (int q = 0; q < 4; q++) lds128(b[q], st + brel[nh * 4 + q] + chk);
#pragma unroll
                for (int j2 = 0; j2 < 2; j2++)
#pragma unroll
                    for (int mt = 0; mt < 2; mt++)
#pragma unroll
                        for (int q = 0; q < 4; q++)
                            mma8(acc[mt][nh * 4 + q],
                                 a[2 * mt][2 * j2], a[2 * mt + 1][2 * j2],
                                 a[2 * mt][2 * j2 + 1], a[2 * mt + 1][2 * j2 + 1],
                                 b[q][2 * j2], b[q][2 * j2 + 1]);
            }
        }
    }

    // ---- Epilogue: direct coalesced STG.64 from register accumulators ----
    float* op = out + (size_t)(m0 + wm * 32 + g) * N_DIM + (n0 + wn * 64 + 2 * c);
#pragma unroll
    for (int mt = 0; mt < 2; mt++) {
#pragma unroll
        for (int nt = 0; nt < 8; nt++) {
            float2 v0 = make_float2(acc[mt][nt][0], acc[mt][nt][1]);
            float2 v1 = make_float2(acc[mt][nt][2], acc[mt][nt][3]);
            *reinterpret_cast<float2*>(op + (size_t)(mt * 16) * N_DIM + nt * 8) = v0;
            *reinterpret_cast<float2*>(op + (size_t)(mt * 16 + 8) * N_DIM + nt * 8) = v1;
        }
    }
}

// ---------------- launch ----------------
extern "C" void kernel_launch(void* const* d_in, const int* in_sizes, int n_in,
                              void* d_out, int out_size) {
    const float* x = (const float*)d_in[0];
    const float* W = (const float*)d_in[1];
    if (n_in >= 2 && in_sizes[0] == N_DIM * K_DIM && in_sizes[1] == B_DIM * K_DIM) {
        const float* t = x; x = W; W = t;   // defensive order swap
    }
    cudaFuncSetAttribute(slb_gemm, cudaFuncAttributeMaxDynamicSharedMemorySize, SMEM_TOTAL);

    repack_x_k<<<(B_DIM * K_DIM) / 256, 256>>>(x);
    repack_w_k<<<(N_DIM * K_DIM) / 256, 256>>>(W);
    slb_gemm<<<(B_DIM / BM) * (N_DIM / BN), 256, SMEM_TOTAL>>>((float*)d_out);
}